// round 8
// baseline (speedup 1.0000x reference)
#include <cuda_runtime.h>
#include <cuda_bf16.h>
#include <cstdint>
#include <cstddef>

#define T_DIM 4096
#define C_DIM 1024
#define D_DIM 256
#define VOCAB 32000

// Shared tile row stride (bf16): 32 data + 8 pad = 40 (80B rows = 5*16B,
// uint4-aligned; ldmatrix phases conflict-free: row r -> word (r*20)%32 =
// {0,20,8,28,16,4,24,12}, distinct 16B bank groups).
#define SMPAD 40
#define STAGES 3

// ---------------- scratch (__device__ globals: allocation-free rule) --------
__device__ __nv_bfloat16 g_x_hi[T_DIM * C_DIM];
__device__ __nv_bfloat16 g_x_lo[T_DIM * C_DIM];
__device__ __nv_bfloat16 g_wt_hi[2][D_DIM * C_DIM];   // W^T [n][k], 0=Wq 1=Wk
__device__ __nv_bfloat16 g_wt_lo[2][D_DIM * C_DIM];
__device__ __nv_bfloat16 g_q_hi[T_DIM * D_DIM];
__device__ __nv_bfloat16 g_q_lo[T_DIM * D_DIM];
__device__ __nv_bfloat16 g_k_hi[T_DIM * D_DIM];
__device__ __nv_bfloat16 g_k_lo[T_DIM * D_DIM];
__device__ float g_c[(size_t)T_DIM * T_DIM];          // lower-tri only
__device__ int   g_idx[T_DIM];

// ---------------------------------------------------------------------------
__global__ void idx_convert_kernel(const int* __restrict__ raw) {
    __shared__ int is64;
    int tid = threadIdx.x;
    if (tid == 0) is64 = 1;
    __syncthreads();
    for (int i = tid; i < 1024; i += blockDim.x)
        if (raw[2 * i + 1] != 0) is64 = 0;
    __syncthreads();
    bool i64 = (is64 != 0);
    for (int i = tid; i < T_DIM; i += blockDim.x)
        g_idx[i] = i64 ? raw[2 * i] : raw[i];
}

__device__ __forceinline__ void split2(float v, __nv_bfloat16& h, __nv_bfloat16& l) {
    h = __float2bfloat16(v);
    l = __float2bfloat16(v - __bfloat162float(h));
}

__global__ void split_x_kernel(const float* __restrict__ x) {
    const int n4 = T_DIM * C_DIM / 4;
    __nv_bfloat162* H = reinterpret_cast<__nv_bfloat162*>(g_x_hi);
    __nv_bfloat162* L = reinterpret_cast<__nv_bfloat162*>(g_x_lo);
    for (int i = blockIdx.x * blockDim.x + threadIdx.x; i < n4;
         i += gridDim.x * blockDim.x) {
        float4 v = reinterpret_cast<const float4*>(x)[i];
        __nv_bfloat16 h0, h1, h2, h3, l0, l1, l2, l3;
        split2(v.x, h0, l0); split2(v.y, h1, l1);
        split2(v.z, h2, l2); split2(v.w, h3, l3);
        H[2 * i]     = __halves2bfloat162(h0, h1);
        H[2 * i + 1] = __halves2bfloat162(h2, h3);
        L[2 * i]     = __halves2bfloat162(l0, l1);
        L[2 * i + 1] = __halves2bfloat162(l2, l3);
    }
}

__global__ void split_w_kernel(const float* __restrict__ Wq,
                               const float* __restrict__ Wk) {
    const float* W = blockIdx.y ? Wk : Wq;
    __nv_bfloat16* hi = g_wt_hi[blockIdx.y];
    __nv_bfloat16* lo = g_wt_lo[blockIdx.y];
    const int total = D_DIM * C_DIM;
    for (int i = blockIdx.x * blockDim.x + threadIdx.x; i < total;
         i += gridDim.x * blockDim.x) {
        int n = i / C_DIM, k = i % C_DIM;
        split2(W[(size_t)k * D_DIM + n], hi[i], lo[i]);
    }
}

// ---------------------------------------------------------------------------
__device__ __forceinline__ void mma16816(float* d, const uint32_t* a,
                                         const uint32_t* b) {
    asm volatile(
        "mma.sync.aligned.m16n8k16.row.col.f32.bf16.bf16.f32 "
        "{%0,%1,%2,%3},{%4,%5,%6,%7},{%8,%9},{%0,%1,%2,%3};"
        : "+f"(d[0]), "+f"(d[1]), "+f"(d[2]), "+f"(d[3])
        : "r"(a[0]), "r"(a[1]), "r"(a[2]), "r"(a[3]), "r"(b[0]), "r"(b[1]));
}

__device__ __forceinline__ uint32_t smem_u32(const void* p) {
    return (uint32_t)__cvta_generic_to_shared(p);
}
__device__ __forceinline__ void ldsm4(uint32_t* r, const void* p) {
    asm volatile("ldmatrix.sync.aligned.m8n8.x4.shared.b16 {%0,%1,%2,%3}, [%4];"
                 : "=r"(r[0]), "=r"(r[1]), "=r"(r[2]), "=r"(r[3])
                 : "r"(smem_u32(p)));
}

__device__ __forceinline__ void cp16(void* smem, const void* gmem) {
    asm volatile("cp.async.cg.shared.global [%0], [%1], 16;"
                 :: "r"(smem_u32(smem)), "l"(gmem));
}
__device__ __forceinline__ void cp_commit() {
    asm volatile("cp.async.commit_group;");
}
template <int N>
__device__ __forceinline__ void cp_wait() {
    asm volatile("cp.async.wait_group %0;" :: "n"(N));
}

// One pipeline stage: 30720 B
struct Tiles {
    __nv_bfloat16 As_hi[128][SMPAD];
    __nv_bfloat16 As_lo[128][SMPAD];
    __nv_bfloat16 Bs_hi[64][SMPAD];
    __nv_bfloat16 Bs_lo[64][SMPAD];
};

// Compute one BK=32 slab. 8 warps (4x2), warp tile 32x32, split-bf16 3-term.
// Term loop is OUTERMOST: consecutive HMMAs hit 8 independent accumulators,
// breaking the 3-deep same-accumulator RAW chain of the naive order.
__device__ __forceinline__ void compute_slab(const Tiles& st, int wm, int wn,
                                             int lane, float acc[2][4][4]) {
    const int ra = (lane & 7) + ((lane >> 3) & 1) * 8;  // A: row within m16
    const int ca = (lane >> 4) * 8;                     // A: k-half select
    const int rb = (lane & 7) + (lane >> 4) * 8;        // B: row within n16
    const int cb = ((lane >> 3) & 1) * 8;               // B: k-half select

    #pragma unroll
    for (int s16 = 0; s16 < 32; s16 += 16) {
        uint32_t ah[2][4], al[2][4], bh[4][2], bl[4][2];
        #pragma unroll
        for (int ms = 0; ms < 2; ms++) {
            int r = wm * 32 + ms * 16 + ra;
            ldsm4(ah[ms], &st.As_hi[r][s16 + ca]);
            ldsm4(al[ms], &st.As_lo[r][s16 + ca]);
        }
        #pragma unroll
        for (int pr = 0; pr < 2; pr++) {
            int r = wn * 32 + pr * 16 + rb;
            uint32_t q[4];
            ldsm4(q, &st.Bs_hi[r][s16 + cb]);
            bh[2 * pr][0] = q[0]; bh[2 * pr][1] = q[1];
            bh[2 * pr + 1][0] = q[2]; bh[2 * pr + 1][1] = q[3];
            ldsm4(q, &st.Bs_lo[r][s16 + cb]);
            bl[2 * pr][0] = q[0]; bl[2 * pr][1] = q[1];
            bl[2 * pr + 1][0] = q[2]; bl[2 * pr + 1][1] = q[3];
        }
        // term hh: 8 independent accumulators
        #pragma unroll
        for (int ms = 0; ms < 2; ms++)
            #pragma unroll
            for (int ns = 0; ns < 4; ns++)
                mma16816(acc[ms][ns], ah[ms], bh[ns]);
        // term hl
        #pragma unroll
        for (int ms = 0; ms < 2; ms++)
            #pragma unroll
            for (int ns = 0; ns < 4; ns++)
                mma16816(acc[ms][ns], ah[ms], bl[ns]);
        // term lh
        #pragma unroll
        for (int ms = 0; ms < 2; ms++)
            #pragma unroll
            for (int ns = 0; ns < 4; ns++)
                mma16816(acc[ms][ns], al[ms], bh[ns]);
    }
}

// Async-load one slab and commit one group.
__device__ __forceinline__ void load_slab(Tiles& st, int tid,
                                          const __nv_bfloat16* aH,
                                          const __nv_bfloat16* aL, size_t ldA,
                                          const __nv_bfloat16* bH,
                                          const __nv_bfloat16* bL, size_t ldB,
                                          int k0) {
    #pragma unroll
    for (int s = 0; s < 2; s++) {
        int idx = tid + s * 256;
        int r = idx >> 2, cw = (idx & 3) * 8;
        size_t go = (size_t)r * ldA + k0 + cw;
        cp16(&st.As_hi[r][cw], &aH[go]);
        cp16(&st.As_lo[r][cw], &aL[go]);
    }
    {
        int r = tid >> 2, cw = (tid & 3) * 8;
        size_t go = (size_t)r * ldB + k0 + cw;
        cp16(&st.Bs_hi[r][cw], &bH[go]);
        cp16(&st.Bs_lo[r][cw], &bL[go]);
    }
    cp_commit();
}

// 3-stage, single-sync-per-slab mainloop.
template <int KT>
__device__ __forceinline__ void gemm_mainloop(
    Tiles* stages, int tid, int wm, int wn, int lane,
    const __nv_bfloat16* aH, const __nv_bfloat16* aL, size_t ldA,
    const __nv_bfloat16* bH, const __nv_bfloat16* bL, size_t ldB,
    float acc[2][4][4]) {

    load_slab(stages[0], tid, aH, aL, ldA, bH, bL, ldB, 0);
    if (KT > 1) load_slab(stages[1], tid, aH, aL, ldA, bH, bL, ldB, 32);

    for (int i = 0; i < KT; i++) {
        cp_wait<1>();          // stage i complete (newest pending may be i+1)
        __syncthreads();       // all warps done with stage (i-1) -> reusable
        int nx = i + STAGES - 1;
        if (nx < KT)
            load_slab(stages[nx % STAGES], tid, aH, aL, ldA, bH, bL, ldB, nx * 32);
        else
            cp_commit();       // keep group count uniform
        compute_slab(stages[i % STAGES], wm, wn, lane, acc);
    }
}

// ---------------------------------------------------------------------------
// qk GEMM: q/k = x @ W. BM=128 BN=64 BK=32, K=1024 (32 slabs).
// ---------------------------------------------------------------------------
__global__ __launch_bounds__(256, 2) void qk_mma_kernel() {
    extern __shared__ Tiles stages[];   // [STAGES]

    const int z = blockIdx.z;
    const int m0 = blockIdx.y * 128;
    const int n0 = blockIdx.x * 64;

    const int tid  = threadIdx.x;
    const int warp = tid >> 5, lane = tid & 31;
    const int wm = warp >> 1, wn = warp & 1;
    const int g = lane >> 2, tg = lane & 3;

    float acc[2][4][4] = {};
    gemm_mainloop<C_DIM / 32>(
        stages, tid, wm, wn, lane,
        g_x_hi + (size_t)m0 * C_DIM, g_x_lo + (size_t)m0 * C_DIM, C_DIM,
        g_wt_hi[z] + (size_t)n0 * C_DIM, g_wt_lo[z] + (size_t)n0 * C_DIM, C_DIM,
        acc);

    __nv_bfloat16* dh = z ? g_k_hi : g_q_hi;
    __nv_bfloat16* dl = z ? g_k_lo : g_q_lo;
    #pragma unroll
    for (int ms = 0; ms < 2; ms++)
        #pragma unroll
        for (int ns = 0; ns < 4; ns++) {
            int m = m0 + wm * 32 + ms * 16 + g;
            int n = n0 + wn * 32 + ns * 8 + tg * 2;
            float* c = acc[ms][ns];
            __nv_bfloat16 h0, h1, l0, l1;
            split2(c[0], h0, l0); split2(c[1], h1, l1);
            *reinterpret_cast<__nv_bfloat162*>(&dh[(size_t)m * D_DIM + n]) =
                __halves2bfloat162(h0, h1);
            *reinterpret_cast<__nv_bfloat162*>(&dl[(size_t)m * D_DIM + n]) =
                __halves2bfloat162(l0, l1);
            split2(c[2], h0, l0); split2(c[3], h1, l1);
            *reinterpret_cast<__nv_bfloat162*>(&dh[(size_t)(m + 8) * D_DIM + n]) =
                __halves2bfloat162(h0, h1);
            *reinterpret_cast<__nv_bfloat162*>(&dl[(size_t)(m + 8) * D_DIM + n]) =
                __halves2bfloat162(l0, l1);
        }
}

// ---------------------------------------------------------------------------
// c GEMM: c = (q @ k^T)/256, triangular grid of 1056 live tiles.
// ---------------------------------------------------------------------------
__global__ __launch_bounds__(256, 2) void c_mma_kernel() {
    extern __shared__ Tiles stages[];   // [STAGES]

    const int bid = blockIdx.x;
    int by = (int)((sqrtf(4.0f * bid + 1.0f) - 1.0f) * 0.5f);
    while (by * by + by > bid) by--;
    while ((by + 1) * (by + 1) + (by + 1) <= bid) by++;
    const int bx = bid - (by * by + by);

    const int t0 = by * 128;
    const int j0 = bx * 64;

    const int tid  = threadIdx.x;
    const int warp = tid >> 5, lane = tid & 31;
    const int wm = warp >> 1, wn = warp & 1;
    const int g = lane >> 2, tg = lane & 3;

    float acc[2][4][4] = {};
    gemm_mainloop<D_DIM / 32>(
        stages, tid, wm, wn, lane,
        g_q_hi + (size_t)t0 * D_DIM, g_q_lo + (size_t)t0 * D_DIM, D_DIM,
        g_k_hi + (size_t)j0 * D_DIM, g_k_lo + (size_t)j0 * D_DIM, D_DIM,
        acc);

    const float scale = 1.0f / 256.0f;
    #pragma unroll
    for (int ms = 0; ms < 2; ms++)
        #pragma unroll
        for (int ns = 0; ns < 4; ns++) {
            int m = t0 + wm * 32 + ms * 16 + g;
            int n = j0 + wn * 32 + ns * 8 + tg * 2;
            float* c = acc[ms][ns];
            *reinterpret_cast<float2*>(&g_c[(size_t)m * T_DIM + n]) =
                make_float2(c[0] * scale, c[1] * scale);
            *reinterpret_cast<float2*>(&g_c[(size_t)(m + 8) * T_DIM + n]) =
                make_float2(c[2] * scale, c[3] * scale);
        }
}

// ---------------------------------------------------------------------------
// scatter: each CTA owns (row t, vocab half). 64KB hist -> 3 CTAs/SM.
// ---------------------------------------------------------------------------
#define HALF_V (VOCAB / 2)

__global__ __launch_bounds__(512) void scatter_kernel(float* __restrict__ out) {
    extern __shared__ float hist[];  // HALF_V floats = 64000 B
    const int t    = blockIdx.x >> 1;
    const int half = blockIdx.x & 1;
    const int vlo  = half * HALF_V;
    const int tid = threadIdx.x;
    const int nt = blockDim.x;

    float4* h4 = reinterpret_cast<float4*>(hist);
    const float4 z4 = make_float4(0.f, 0.f, 0.f, 0.f);
    for (int i = tid; i < HALF_V / 4; i += nt) h4[i] = z4;
    __syncthreads();

    const float* crow = &g_c[(size_t)t * T_DIM];
    for (int j = tid; j <= t; j += nt) {
        unsigned v = (unsigned)(g_idx[j] - vlo);
        if (v < (unsigned)HALF_V) atomicAdd(&hist[v], crow[j]);
    }
    __syncthreads();

    float4* o4 = reinterpret_cast<float4*>(out + (size_t)t * VOCAB + vlo);
    for (int i = tid; i < HALF_V / 4; i += nt) __stcs(&o4[i], h4[i]);
}

// ---------------------------------------------------------------------------
extern "C" void kernel_launch(void* const* d_in, const int* in_sizes, int n_in,
                              void* d_out, int out_size) {
    const float* x      = (const float*)d_in[0];
    const int*   idxraw = (const int*)d_in[1];
    const float* Wq     = (const float*)d_in[2];
    const float* Wk     = (const float*)d_in[3];
    float*       out    = (float*)d_out;
    (void)in_sizes; (void)n_in; (void)out_size;

    const int PIPE_SMEM = STAGES * (int)sizeof(Tiles);   // 92160 B

    idx_convert_kernel<<<1, 256>>>(idxraw);
    split_x_kernel<<<1024, 256>>>(x);
    split_w_kernel<<<dim3(64, 2), 256>>>(Wq, Wk);

    cudaFuncSetAttribute(qk_mma_kernel,
                         cudaFuncAttributeMaxDynamicSharedMemorySize, PIPE_SMEM);
    qk_mma_kernel<<<dim3(4, 32, 2), 256, PIPE_SMEM>>>();

    cudaFuncSetAttribute(c_mma_kernel,
                         cudaFuncAttributeMaxDynamicSharedMemorySize, PIPE_SMEM);
    c_mma_kernel<<<1056, 256, PIPE_SMEM>>>();

    cudaFuncSetAttribute(scatter_kernel,
                         cudaFuncAttributeMaxDynamicSharedMemorySize,
                         HALF_V * (int)sizeof(float));
    scatter_kernel<<<2 * T_DIM, 512, HALF_V * sizeof(float)>>>(out);
}